// round 1
// baseline (speedup 1.0000x reference)
#include <cuda_runtime.h>
#include <cuda_bf16.h>
#include <cstdint>

#define NUM_DST   10000
#define NUM_EDGES 600000
#define DN   100
#define DE   172
#define DTF  100
#define DOUT 128
#define KDIM (DN + DE + DTF)   // 372
#define ET   32                 // edges per block in KV kernel

// ---------------- scratch (device globals: no runtime alloc allowed) --------
__device__ float    g_qnodes[NUM_DST * DOUT];
__device__ float    g_V[(size_t)NUM_EDGES * DOUT];
__device__ float    g_scores[NUM_EDGES * 2];
__device__ unsigned g_m[NUM_DST * 2];
__device__ float    g_z[NUM_DST * 2];
__device__ float    g_agg[NUM_DST * DOUT];
__device__ float    g_qbias[DOUT];
__device__ float    g_absum[2];

// order-preserving float<->uint encoding for atomicMax on floats
__device__ __forceinline__ unsigned ford(float f) {
    unsigned u = __float_as_uint(f);
    return (u & 0x80000000u) ? ~u : (u | 0x80000000u);
}
__device__ __forceinline__ float orddec(unsigned u) {
    return (u & 0x80000000u) ? __uint_as_float(u & 0x7fffffffu)
                             : __uint_as_float(~u);
}

// ---------------- kernel 0: init + derived constants ------------------------
__global__ void init_kernel(const float* __restrict__ time_b,
                            const float* __restrict__ wq,
                            const float* __restrict__ bq,
                            const float* __restrict__ att_bias)
{
    int idx = blockIdx.x * blockDim.x + threadIdx.x;
    if (idx < NUM_DST * DOUT) g_agg[idx] = 0.f;
    if (idx < NUM_DST * 2) { g_m[idx] = 0u; g_z[idx] = 0.f; }
    if (idx < DOUT) {
        // zero-time Q contribution: cos(time_b) @ wq[DN:] + bq  (constant row)
        float acc = bq[idx];
        #pragma unroll 4
        for (int t = 0; t < DTF; t++)
            acc += cosf(time_b[t]) * wq[(DN + t) * DOUT + idx];
        g_qbias[idx] = acc;
    }
    if (idx < 2) {
        float s = 0.f;
        for (int j = 0; j < DOUT / 2; j++) s += att_bias[idx * (DOUT / 2) + j];
        g_absum[idx] = s;
    }
}

// ---------------- kernel 1: Q per dst node ----------------------------------
__global__ __launch_bounds__(128) void qnode_kernel(const float* __restrict__ h,
                                                    const float* __restrict__ wq)
{
    int dst = blockIdx.x;
    int tid = threadIdx.x;
    __shared__ float s_h[DN];
    if (tid < DN) s_h[tid] = h[(size_t)dst * DN + tid];
    __syncthreads();
    float acc = g_qbias[tid];
    #pragma unroll 4
    for (int k = 0; k < DN; k++)
        acc += s_h[k] * wq[k * DOUT + tid];
    g_qnodes[dst * DOUT + tid] = acc;
}

// ---------------- kernel 2: fused KV GEMM + scores + segment max ------------
// block = 256 threads, 32 edges. thread t: group g=t>>6 owns 8 edges,
// column pair c0=(t&63)*2. warp = one head of 8 edges -> shuffle reduce.
__global__ __launch_bounds__(256) void kv_kernel(
    const float* __restrict__ h,   const float* __restrict__ ef,
    const float* __restrict__ dt,  const int*   __restrict__ dst_idx,
    const float* __restrict__ time_w, const float* __restrict__ time_b,
    const float* __restrict__ wk,  const float* __restrict__ bk,
    const float* __restrict__ wv,  const float* __restrict__ bv)
{
    __shared__ float s_kv[ET][KDIM + 4];   // +4 pad; loads are broadcast anyway
    const int e_base = blockIdx.x * ET;
    const int tid = threadIdx.x;

    // ---- build kv_in tile: [h_src | ef | cos(dt*w+b)] ----
    for (int idx = tid; idx < ET * KDIM; idx += 256) {
        int e = idx / KDIM;
        int j = idx - e * KDIM;
        int edge = e_base + e;
        float v;
        if (j < DN) {
            v = h[(size_t)(NUM_DST + edge) * DN + j];
        } else if (j < DN + DE) {
            v = ef[(size_t)edge * DE + (j - DN)];
        } else {
            int t = j - DN - DE;
            v = __cosf(dt[edge] * time_w[t] + time_b[t]);
        }
        s_kv[e][j] = v;
    }
    __syncthreads();

    const int lane64 = tid & 63;   // column-pair index (cols 2*lane64, +1)
    const int g = tid >> 6;        // edge group (8 edges each)
    const float2* __restrict__ wk2 = (const float2*)wk;
    const float2* __restrict__ wv2 = (const float2*)wv;

    float2 aK[8], aV[8];
    #pragma unroll
    for (int i = 0; i < 8; i++) {
        aK[i] = make_float2(0.f, 0.f);
        aV[i] = make_float2(0.f, 0.f);
    }

    #pragma unroll 2
    for (int k = 0; k < KDIM; k++) {
        float2 wkk = wk2[k * (DOUT / 2) + lane64];
        float2 wvv = wv2[k * (DOUT / 2) + lane64];
        #pragma unroll
        for (int i = 0; i < 8; i++) {
            float x = s_kv[g * 8 + i][k];
            aK[i].x = fmaf(x, wkk.x, aK[i].x);
            aK[i].y = fmaf(x, wkk.y, aK[i].y);
            aV[i].x = fmaf(x, wvv.x, aV[i].x);
            aV[i].y = fmaf(x, wvv.y, aV[i].y);
        }
    }

    float2 bk2 = ((const float2*)bk)[lane64];
    float2 bv2 = ((const float2*)bv)[lane64];

    // ---- write V (with bias) to scratch, compute Q.K partials ----
    float p[8];
    #pragma unroll
    for (int i = 0; i < 8; i++) {
        int edge = e_base + g * 8 + i;
        aK[i].x += bk2.x; aK[i].y += bk2.y;
        float2 v = make_float2(aV[i].x + bv2.x, aV[i].y + bv2.y);
        ((float2*)g_V)[(size_t)edge * (DOUT / 2) + lane64] = v;
        int d = dst_idx[edge];
        float2 q = ((const float2*)g_qnodes)[(size_t)d * (DOUT / 2) + lane64];
        p[i] = q.x * aK[i].x + q.y * aK[i].y;
    }

    // warp holds one head's partials for 8 edges -> butterfly reduce
    #pragma unroll
    for (int off = 16; off > 0; off >>= 1) {
        #pragma unroll
        for (int i = 0; i < 8; i++)
            p[i] += __shfl_xor_sync(0xffffffffu, p[i], off);
    }

    int lane = tid & 31;
    int head = (tid >> 5) & 1;     // warps alternate heads within a group
    if (lane < 8) {
        int edge = e_base + g * 8 + lane;
        float sc = p[lane] + g_absum[head];
        sc = sc > 0.f ? sc : 0.2f * sc;          // leaky_relu(0.2)
        g_scores[edge * 2 + head] = sc;
        atomicMax(&g_m[dst_idx[edge] * 2 + head], ford(sc));
    }
}

// ---------------- kernel 3: exp(s - m), z = segment_sum ---------------------
__global__ void expz_kernel(const int* __restrict__ dst_idx)
{
    int idx = blockIdx.x * blockDim.x + threadIdx.x;
    if (idx >= NUM_EDGES * 2) return;
    int e = idx >> 1, hh = idx & 1;
    int dh = dst_idx[e] * 2 + hh;
    float ex = __expf(g_scores[idx] - orddec(g_m[dh]));
    g_scores[idx] = ex;
    atomicAdd(&g_z[dh], ex);
}

// ---------------- kernel 4: agg += att * V (one warp per edge) --------------
__global__ __launch_bounds__(256) void agg_kernel(const int* __restrict__ dst_idx)
{
    int w = (blockIdx.x * blockDim.x + threadIdx.x) >> 5;
    if (w >= NUM_EDGES) return;
    int lane = threadIdx.x & 31;
    int edge = w;
    int dst = dst_idx[edge];
    int head = lane >> 4;                       // 16 lanes (64 cols) per head
    float att = g_scores[edge * 2 + head] / g_z[dst * 2 + head];
    float4 v = ((const float4*)g_V)[(size_t)edge * (DOUT / 4) + lane];
    v.x *= att; v.y *= att; v.z *= att; v.w *= att;
    float* ptr = &g_agg[dst * DOUT + lane * 4];
    asm volatile("red.global.add.v4.f32 [%0], {%1,%2,%3,%4};"
                 :: "l"(ptr), "f"(v.x), "f"(v.y), "f"(v.z), "f"(v.w)
                 : "memory");
}

// ---------------- kernel 5: output GEMM + relu + layernorm ------------------
__global__ __launch_bounds__(128) void out_kernel(
    const float* __restrict__ h,    const float* __restrict__ wout,
    const float* __restrict__ bout, const float* __restrict__ ln_g,
    const float* __restrict__ ln_b, float* __restrict__ out)
{
    int dst = blockIdx.x;
    int tid = threadIdx.x;
    __shared__ float s_in[DOUT + DN];
    __shared__ float s_sum[4], s_sq[4];
    s_in[tid] = g_agg[dst * DOUT + tid];
    if (tid < DN) s_in[DOUT + tid] = h[(size_t)dst * DN + tid];
    __syncthreads();

    float acc = bout[tid];
    #pragma unroll 4
    for (int k = 0; k < DOUT + DN; k++)
        acc = fmaf(s_in[k], wout[k * DOUT + tid], acc);
    acc = fmaxf(acc, 0.f);

    float s1 = acc, s2 = acc * acc;
    #pragma unroll
    for (int off = 16; off > 0; off >>= 1) {
        s1 += __shfl_xor_sync(0xffffffffu, s1, off);
        s2 += __shfl_xor_sync(0xffffffffu, s2, off);
    }
    int warp = tid >> 5;
    if ((tid & 31) == 0) { s_sum[warp] = s1; s_sq[warp] = s2; }
    __syncthreads();
    float t1 = s_sum[0] + s_sum[1] + s_sum[2] + s_sum[3];
    float t2 = s_sq[0]  + s_sq[1]  + s_sq[2]  + s_sq[3];
    float mu  = t1 * (1.f / DOUT);
    float var = t2 * (1.f / DOUT) - mu * mu;
    out[(size_t)dst * DOUT + tid] =
        (acc - mu) * rsqrtf(var + 1e-5f) * ln_g[tid] + ln_b[tid];
}

// ---------------- launch ----------------------------------------------------
extern "C" void kernel_launch(void* const* d_in, const int* in_sizes, int n_in,
                              void* d_out, int out_size)
{
    // input order: h, ef, dt, dst_idx, [num_dst scalar?], time_w, time_b,
    //              wq, bq, wk, bk, wv, bv, att_bias, wout, bout, ln_g, ln_b
    int off = (n_in >= 18 && in_sizes[4] == 1) ? 1 : 0;
    const float* h        = (const float*)d_in[0];
    const float* ef       = (const float*)d_in[1];
    const float* dt       = (const float*)d_in[2];
    const int*   dst_idx  = (const int*)  d_in[3];
    const float* time_w   = (const float*)d_in[4 + off];
    const float* time_b   = (const float*)d_in[5 + off];
    const float* wq       = (const float*)d_in[6 + off];
    const float* bq       = (const float*)d_in[7 + off];
    const float* wk       = (const float*)d_in[8 + off];
    const float* bk       = (const float*)d_in[9 + off];
    const float* wv       = (const float*)d_in[10 + off];
    const float* bv       = (const float*)d_in[11 + off];
    const float* att_bias = (const float*)d_in[12 + off];
    const float* wout     = (const float*)d_in[13 + off];
    const float* bout     = (const float*)d_in[14 + off];
    const float* ln_g     = (const float*)d_in[15 + off];
    const float* ln_b     = (const float*)d_in[16 + off];
    float* out = (float*)d_out;

    init_kernel<<<(NUM_DST * DOUT + 255) / 256, 256>>>(time_b, wq, bq, att_bias);
    qnode_kernel<<<NUM_DST, 128>>>(h, wq);
    kv_kernel<<<NUM_EDGES / ET, 256>>>(h, ef, dt, dst_idx, time_w, time_b,
                                       wk, bk, wv, bv);
    expz_kernel<<<(NUM_EDGES * 2 + 255) / 256, 256>>>(dst_idx);
    agg_kernel<<<(NUM_EDGES * 32 + 255) / 256, 256>>>(dst_idx);
    out_kernel<<<NUM_DST, 128>>>(h, wout, bout, ln_g, ln_b, out);
}

// round 2
// speedup vs baseline: 1.7406x; 1.7406x over previous
#include <cuda_runtime.h>
#include <cuda_bf16.h>
#include <cstdint>

#define NUM_DST   10000
#define NUM_EDGES 600000
#define DN   100
#define DE   172
#define DTF  100
#define DOUT 128
#define KDIM (DN + DE + DTF)   // 372
#define NKC  12                // k-chunks of 32 (384 padded)

// ---------------- scratch (device globals: no runtime alloc allowed) --------
__device__ float    g_qnodes[NUM_DST * DOUT];
__device__ float    g_Pq[(size_t)NUM_DST * KDIM * 2];
__device__ float    g_scores[NUM_EDGES * 2];
__device__ unsigned g_m[NUM_DST * 2];
__device__ float    g_z[NUM_DST * 2];
__device__ float    g_agg[NUM_DST * DOUT];
__device__ float    g_qbias[DOUT];
__device__ float    g_absum[2];

// order-preserving float<->uint encoding for atomicMax on floats
__device__ __forceinline__ unsigned ford(float f) {
    unsigned u = __float_as_uint(f);
    return (u & 0x80000000u) ? ~u : (u | 0x80000000u);
}
__device__ __forceinline__ float orddec(unsigned u) {
    return (u & 0x80000000u) ? __uint_as_float(u & 0x7fffffffu)
                             : __uint_as_float(~u);
}

__device__ __forceinline__ uint32_t to_tf32(float f) {
    uint32_t r;
    asm("cvt.rna.tf32.f32 %0, %1;" : "=r"(r) : "f"(f));
    return r;
}

// ---------------- kernel 0: init + derived constants ------------------------
__global__ void init_kernel(const float* __restrict__ time_b,
                            const float* __restrict__ wq,
                            const float* __restrict__ bq,
                            const float* __restrict__ att_bias)
{
    int idx = blockIdx.x * blockDim.x + threadIdx.x;
    if (idx < NUM_DST * DOUT) g_agg[idx] = 0.f;
    if (idx < NUM_DST * 2) { g_m[idx] = 0u; g_z[idx] = 0.f; }
    if (idx < DOUT) {
        float acc = bq[idx];
        #pragma unroll 4
        for (int t = 0; t < DTF; t++)
            acc += cosf(time_b[t]) * wq[(DN + t) * DOUT + idx];
        g_qbias[idx] = acc;
    }
    if (idx < 2) {
        float s = 0.f;
        for (int j = 0; j < DOUT / 2; j++) s += att_bias[idx * (DOUT / 2) + j];
        g_absum[idx] = s;
    }
}

// ---------------- kernel 1: Q per dst node (4 dst / block) ------------------
__global__ __launch_bounds__(128) void qnode_kernel(const float* __restrict__ h,
                                                    const float* __restrict__ wq)
{
    int dbase = blockIdx.x * 4;
    int c = threadIdx.x;
    __shared__ float sh[4][DN];
    for (int i = c; i < 4 * DN; i += 128) {
        int dl = i / DN, k = i - dl * DN;
        sh[dl][k] = h[(size_t)(dbase + dl) * DN + k];
    }
    __syncthreads();
    float qb = g_qbias[c];
    float a0 = qb, a1 = qb, a2 = qb, a3 = qb;
    #pragma unroll 4
    for (int k = 0; k < DN; k++) {
        float w = wq[k * DOUT + c];
        a0 = fmaf(sh[0][k], w, a0);
        a1 = fmaf(sh[1][k], w, a1);
        a2 = fmaf(sh[2][k], w, a2);
        a3 = fmaf(sh[3][k], w, a3);
    }
    g_qnodes[(dbase + 0) * DOUT + c] = a0;
    g_qnodes[(dbase + 1) * DOUT + c] = a1;
    g_qnodes[(dbase + 2) * DOUT + c] = a2;
    g_qnodes[(dbase + 3) * DOUT + c] = a3;
}

// ---------------- kernel 1b: Pq[d,k,h] = sum_c qn[d,64h+c] * wk[k,64h+c] ----
// grid (157, 6): 64-dst x 64-k tiles. block 256.
__global__ __launch_bounds__(256) void pq_kernel(const float* __restrict__ wk)
{
    __shared__ float qs[64][129];
    __shared__ float ws[64][129];
    int dbase = blockIdx.x * 64;
    int kbase = blockIdx.y * 64;
    int tid = threadIdx.x;
    for (int i = tid; i < 64 * 128; i += 256) {
        int r = i >> 7, c = i & 127;
        int d = dbase + r;
        qs[r][c] = (d < NUM_DST) ? g_qnodes[d * DOUT + c] : 0.f;
        int k = kbase + r;
        ws[r][c] = (k < KDIM) ? wk[k * DOUT + c] : 0.f;
    }
    __syncthreads();
    int tx = tid & 15, ty = tid >> 4;   // tx: k-quad, ty: dst-quad
    float acc[2][4][4];
    #pragma unroll
    for (int hh = 0; hh < 2; hh++)
        #pragma unroll
        for (int i = 0; i < 4; i++)
            #pragma unroll
            for (int j = 0; j < 4; j++) acc[hh][i][j] = 0.f;

    #pragma unroll 1
    for (int hh = 0; hh < 2; hh++) {
        for (int c = 0; c < 64; c++) {
            float q[4], w[4];
            #pragma unroll
            for (int i = 0; i < 4; i++) q[i] = qs[ty * 4 + i][hh * 64 + c];
            #pragma unroll
            for (int j = 0; j < 4; j++) w[j] = ws[tx * 4 + j][hh * 64 + c];
            #pragma unroll
            for (int i = 0; i < 4; i++)
                #pragma unroll
                for (int j = 0; j < 4; j++)
                    acc[hh][i][j] = fmaf(q[i], w[j], acc[hh][i][j]);
        }
    }
    #pragma unroll
    for (int i = 0; i < 4; i++) {
        int d = dbase + ty * 4 + i;
        if (d >= NUM_DST) continue;
        #pragma unroll
        for (int j = 0; j < 4; j++) {
            int k = kbase + tx * 4 + j;
            if (k >= KDIM) continue;
            g_Pq[((size_t)d * KDIM + k) * 2 + 0] = acc[0][i][j];
            g_Pq[((size_t)d * KDIM + k) * 2 + 1] = acc[1][i][j];
        }
    }
}

// ---------------- kernel 2a: scores (one warp per edge) ---------------------
__global__ __launch_bounds__(256) void score_kernel(
    const float* __restrict__ h,   const float* __restrict__ ef,
    const float* __restrict__ dt,  const int*   __restrict__ dst_idx,
    const float* __restrict__ time_w, const float* __restrict__ time_b)
{
    int e = (blockIdx.x * 256 + threadIdx.x) >> 5;
    if (e >= NUM_EDGES) return;
    int lane = threadIdx.x & 31;
    float td = dt[e];
    int d = dst_idx[e];
    const float2* __restrict__ pq = (const float2*)&g_Pq[(size_t)d * KDIM * 2];
    float a0 = 0.f, a1 = 0.f;
    #pragma unroll 1
    for (int it = 0; it < 12; it++) {
        int k = it * 32 + lane;
        if (k < KDIM) {
            float v;
            if (k < DN)            v = h[(size_t)(NUM_DST + e) * DN + k];
            else if (k < DN + DE)  v = ef[(size_t)e * DE + (k - DN)];
            else { int t = k - DN - DE; v = __cosf(td * time_w[t] + time_b[t]); }
            float2 p = pq[k];
            a0 = fmaf(v, p.x, a0);
            a1 = fmaf(v, p.y, a1);
        }
    }
    #pragma unroll
    for (int off = 16; off > 0; off >>= 1) {
        a0 += __shfl_xor_sync(0xffffffffu, a0, off);
        a1 += __shfl_xor_sync(0xffffffffu, a1, off);
    }
    if (lane == 0) {
        float s0 = a0 + g_absum[0]; s0 = s0 > 0.f ? s0 : 0.2f * s0;
        float s1 = a1 + g_absum[1]; s1 = s1 > 0.f ? s1 : 0.2f * s1;
        g_scores[e * 2 + 0] = s0;
        g_scores[e * 2 + 1] = s1;
        atomicMax(&g_m[d * 2 + 0], ford(s0));
        atomicMax(&g_m[d * 2 + 1], ford(s1));
    }
}

// ---------------- kernel 3: exp(s - m), z = segment_sum ---------------------
__global__ void expz_kernel(const int* __restrict__ dst_idx)
{
    int idx = blockIdx.x * blockDim.x + threadIdx.x;
    if (idx >= NUM_EDGES * 2) return;
    int e = idx >> 1, hh = idx & 1;
    int dh = dst_idx[e] * 2 + hh;
    float ex = __expf(g_scores[idx] - orddec(g_m[dh]));
    g_scores[idx] = ex;
    atomicAdd(&g_z[dh], ex);
}

// ---------------- kernel 2b: tf32-MMA V GEMM fused with aggregation ---------
// 64 edges x 128 cols per block. 8 warps: wm in {0,1} (32 edges), wn in {0..3}
// (32 cols). k streamed in chunks of 32, mma.m16n8k8 tf32.
__global__ __launch_bounds__(256, 2) void vagg_kernel(
    const float* __restrict__ h,   const float* __restrict__ ef,
    const float* __restrict__ dt,  const int*   __restrict__ dst_idx,
    const float* __restrict__ time_w, const float* __restrict__ time_b,
    const float* __restrict__ wv)
{
    __shared__ uint32_t As[64][36];    // 64 edges x 32 k (tf32 bits), pad 4
    __shared__ uint32_t Bs[32][136];   // 32 k x 128 cols (tf32 bits), pad 8
    const int e_base = blockIdx.x * 64;
    const int tid  = threadIdx.x;
    const int lane = tid & 31;
    const int wid  = tid >> 5;
    const int wm   = wid & 1;
    const int wn   = wid >> 1;

    float acc[2][4][4];
    #pragma unroll
    for (int mf = 0; mf < 2; mf++)
        #pragma unroll
        for (int nf = 0; nf < 4; nf++)
            #pragma unroll
            for (int r = 0; r < 4; r++) acc[mf][nf][r] = 0.f;

    for (int kc = 0; kc < NKC; kc++) {
        __syncthreads();
        // fill A chunk: 64x32, 8 elems/thread, warp handles one edge row
        #pragma unroll
        for (int rep = 0; rep < 8; rep++) {
            int i = tid + rep * 256;
            int el = i >> 5, kl = i & 31;
            int j = kc * 32 + kl;
            int edge = e_base + el;
            float v = 0.f;
            if (j < DN)               v = h[(size_t)(NUM_DST + edge) * DN + j];
            else if (j < DN + DE)     v = ef[(size_t)edge * DE + (j - DN)];
            else if (j < KDIM) {
                int t = j - DN - DE;
                v = __cosf(dt[edge] * time_w[t] + time_b[t]);
            }
            As[el][kl] = to_tf32(v);
        }
        // fill B chunk: 32x128, 16 elems/thread
        #pragma unroll
        for (int rep = 0; rep < 16; rep++) {
            int i = tid + rep * 256;
            int r = i >> 7, c = i & 127;
            int j = kc * 32 + r;
            float v = (j < KDIM) ? wv[j * DOUT + c] : 0.f;
            Bs[r][c] = to_tf32(v);
        }
        __syncthreads();

        #pragma unroll
        for (int ks = 0; ks < 4; ks++) {
            uint32_t a[2][4];
            int arow = lane >> 2, acol = (lane & 3) + ks * 8;
            #pragma unroll
            for (int mf = 0; mf < 2; mf++) {
                int rb = wm * 32 + mf * 16 + arow;
                a[mf][0] = As[rb][acol];
                a[mf][1] = As[rb + 8][acol];
                a[mf][2] = As[rb][acol + 4];
                a[mf][3] = As[rb + 8][acol + 4];
            }
            uint32_t b[4][2];
            int brow = (lane & 3) + ks * 8;
            #pragma unroll
            for (int nf = 0; nf < 4; nf++) {
                int bn = wn * 32 + nf * 8 + (lane >> 2);
                b[nf][0] = Bs[brow][bn];
                b[nf][1] = Bs[brow + 4][bn];
            }
            #pragma unroll
            for (int mf = 0; mf < 2; mf++)
                #pragma unroll
                for (int nf = 0; nf < 4; nf++) {
                    asm volatile(
                        "mma.sync.aligned.m16n8k8.row.col.f32.tf32.tf32.f32 "
                        "{%0,%1,%2,%3}, {%4,%5,%6,%7}, {%8,%9}, {%0,%1,%2,%3};"
                        : "+f"(acc[mf][nf][0]), "+f"(acc[mf][nf][1]),
                          "+f"(acc[mf][nf][2]), "+f"(acc[mf][nf][3])
                        : "r"(a[mf][0]), "r"(a[mf][1]), "r"(a[mf][2]), "r"(a[mf][3]),
                          "r"(b[nf][0]), "r"(b[nf][1]));
                }
        }
    }

    // epilogue: scale by att, atomically accumulate into g_agg
    const int head = wn >> 1;
    #pragma unroll
    for (int mf = 0; mf < 2; mf++) {
        #pragma unroll
        for (int rs = 0; rs < 2; rs++) {
            int e = e_base + wm * 32 + mf * 16 + rs * 8 + (lane >> 2);
            int d = dst_idx[e];
            float att = g_scores[e * 2 + head] / g_z[d * 2 + head];
            #pragma unroll
            for (int nf = 0; nf < 4; nf++) {
                int col = wn * 32 + nf * 8 + 2 * (lane & 3);
                float vx = acc[mf][nf][rs * 2 + 0] * att;
                float vy = acc[mf][nf][rs * 2 + 1] * att;
                float* ptr = &g_agg[d * DOUT + col];
                asm volatile("red.global.add.v2.f32 [%0], {%1,%2};"
                             :: "l"(ptr), "f"(vx), "f"(vy) : "memory");
            }
        }
    }
}

// ---------------- kernel 5: output GEMM + relu + layernorm (4 dst/block) ----
__global__ __launch_bounds__(128) void out_kernel(
    const float* __restrict__ h,    const float* __restrict__ wout,
    const float* __restrict__ bout, const float* __restrict__ bv,
    const float* __restrict__ ln_g, const float* __restrict__ ln_b,
    float* __restrict__ out)
{
    int dbase = blockIdx.x * 4;
    int c = threadIdx.x;
    __shared__ float sin[4][DOUT + DN];
    __shared__ float red1[4][4], red2[4][4];
    for (int i = c; i < 4 * (DOUT + DN); i += 128) {
        int dl = i / (DOUT + DN), k = i - dl * (DOUT + DN);
        int d = dbase + dl;
        float v;
        if (k < DOUT)
            v = g_agg[d * DOUT + k] + (g_z[d * 2 + (k >> 6)] > 0.f ? bv[k] : 0.f);
        else
            v = h[(size_t)d * DN + (k - DOUT)];
        sin[dl][k] = v;
    }
    __syncthreads();

    float b0 = bout[c];
    float a[4] = {b0, b0, b0, b0};
    #pragma unroll 4
    for (int k = 0; k < DOUT + DN; k++) {
        float w = wout[k * DOUT + c];
        #pragma unroll
        for (int d = 0; d < 4; d++) a[d] = fmaf(sin[d][k], w, a[d]);
    }
    float s1[4], s2[4];
    #pragma unroll
    for (int d = 0; d < 4; d++) {
        a[d] = fmaxf(a[d], 0.f);
        s1[d] = a[d];
        s2[d] = a[d] * a[d];
    }
    #pragma unroll
    for (int off = 16; off > 0; off >>= 1) {
        #pragma unroll
        for (int d = 0; d < 4; d++) {
            s1[d] += __shfl_xor_sync(0xffffffffu, s1[d], off);
            s2[d] += __shfl_xor_sync(0xffffffffu, s2[d], off);
        }
    }
    int warp = c >> 5;
    if ((c & 31) == 0) {
        #pragma unroll
        for (int d = 0; d < 4; d++) { red1[d][warp] = s1[d]; red2[d][warp] = s2[d]; }
    }
    __syncthreads();
    #pragma unroll
    for (int d = 0; d < 4; d++) {
        float t1 = red1[d][0] + red1[d][1] + red1[d][2] + red1[d][3];
        float t2 = red2[d][0] + red2[d][1] + red2[d][2] + red2[d][3];
        float mu  = t1 * (1.f / DOUT);
        float var = t2 * (1.f / DOUT) - mu * mu;
        out[(size_t)(dbase + d) * DOUT + c] =
            (a[d] - mu) * rsqrtf(var + 1e-5f) * ln_g[c] + ln_b[c];
    }
}

// ---------------- launch ----------------------------------------------------
extern "C" void kernel_launch(void* const* d_in, const int* in_sizes, int n_in,
                              void* d_out, int out_size)
{
    int off = (n_in >= 18 && in_sizes[4] == 1) ? 1 : 0;
    const float* h        = (const float*)d_in[0];
    const float* ef       = (const float*)d_in[1];
    const float* dt       = (const float*)d_in[2];
    const int*   dst_idx  = (const int*)  d_in[3];
    const float* time_w   = (const float*)d_in[4 + off];
    const float* time_b   = (const float*)d_in[5 + off];
    const float* wq       = (const float*)d_in[6 + off];
    const float* bq       = (const float*)d_in[7 + off];
    const float* wk       = (const float*)d_in[8 + off];
    const float* bk       = (const float*)d_in[9 + off];   (void)bk;
    const float* wv       = (const float*)d_in[10 + off];
    const float* bv       = (const float*)d_in[11 + off];
    const float* att_bias = (const float*)d_in[12 + off];
    const float* wout     = (const float*)d_in[13 + off];
    const float* bout     = (const float*)d_in[14 + off];
    const float* ln_g     = (const float*)d_in[15 + off];
    const float* ln_b     = (const float*)d_in[16 + off];
    float* out = (float*)d_out;

    init_kernel<<<(NUM_DST * DOUT + 255) / 256, 256>>>(time_b, wq, bq, att_bias);
    qnode_kernel<<<NUM_DST / 4, 128>>>(h, wq);
    pq_kernel<<<dim3((NUM_DST + 63) / 64, (KDIM + 63) / 64), 256>>>(wk);
    score_kernel<<<NUM_EDGES / 8, 256>>>(h, ef, dt, dst_idx, time_w, time_b);
    expz_kernel<<<(NUM_EDGES * 2 + 255) / 256, 256>>>(dst_idx);
    vagg_kernel<<<NUM_EDGES / 64, 256>>>(h, ef, dt, dst_idx, time_w, time_b, wv);
    out_kernel<<<NUM_DST / 4, 128>>>(h, wout, bout, bv, ln_g, ln_b, out);
}

// round 3
// speedup vs baseline: 3.1941x; 1.8351x over previous
#include <cuda_runtime.h>
#include <cuda_bf16.h>
#include <cstdint>

#define NUM_DST   10000
#define NUM_EDGES 600000
#define DN   100
#define DE   172
#define DTF  100
#define DOUT 128
#define KDIM (DN + DE + DTF)   // 372
#define KPAD 384
#define NKC  12                // k-chunks of 32
#define ET2  128               // edges per tile in vagg
#define NTILES ((NUM_EDGES + ET2 - 1) / ET2)   // 4688
#define VAGG_GRID 304
#define VAGG_SMEM (KPAD * DOUT * 4 + 2 * ET2 * 32 * 4)   // 229376 B

// ---------------- scratch (device globals: no runtime alloc allowed) --------
__device__ float g_qnodes[NUM_DST * DOUT];
__device__ float g_qbk[NUM_DST * 2];
__device__ float g_Pq[(size_t)NUM_DST * KDIM * 2];
__device__ float g_scores[NUM_EDGES * 2];
__device__ float g_z[NUM_DST * 2];
__device__ float g_agg[NUM_DST * DOUT];
__device__ float g_qbias[DOUT];
__device__ float g_absum[2];

__device__ __forceinline__ uint32_t to_tf32(float f) {
    uint32_t r;
    asm("cvt.rna.tf32.f32 %0, %1;" : "=r"(r) : "f"(f));
    return r;
}

// ---------------- kernel 0: init + derived constants ------------------------
__global__ void init_kernel(const float* __restrict__ time_b,
                            const float* __restrict__ wq,
                            const float* __restrict__ bq,
                            const float* __restrict__ att_bias)
{
    int idx = blockIdx.x * blockDim.x + threadIdx.x;
    if (idx < NUM_DST * DOUT) g_agg[idx] = 0.f;
    if (idx < NUM_DST * 2) g_z[idx] = 0.f;
    if (idx < DOUT) {
        float acc = bq[idx];
        #pragma unroll 4
        for (int t = 0; t < DTF; t++)
            acc += cosf(time_b[t]) * wq[(DN + t) * DOUT + idx];
        g_qbias[idx] = acc;
    }
    if (idx < 2) {
        float s = 0.f;
        for (int j = 0; j < DOUT / 2; j++) s += att_bias[idx * (DOUT / 2) + j];
        g_absum[idx] = s;
    }
}

// ---------------- kernel 1: Q per dst node (4 dst / block) + Q.bk ----------
__global__ __launch_bounds__(128) void qnode_kernel(const float* __restrict__ h,
                                                    const float* __restrict__ wq,
                                                    const float* __restrict__ bk)
{
    int dbase = blockIdx.x * 4;
    int c = threadIdx.x;
    __shared__ float sh[4][DN];
    __shared__ float part[4][4];
    for (int i = c; i < 4 * DN; i += 128) {
        int dl = i / DN, k = i - dl * DN;
        sh[dl][k] = h[(size_t)(dbase + dl) * DN + k];
    }
    __syncthreads();
    float qb = g_qbias[c];
    float a[4] = {qb, qb, qb, qb};
    #pragma unroll 4
    for (int k = 0; k < DN; k++) {
        float w = wq[k * DOUT + c];
        #pragma unroll
        for (int d = 0; d < 4; d++) a[d] = fmaf(sh[d][k], w, a[d]);
    }
    #pragma unroll
    for (int d = 0; d < 4; d++)
        g_qnodes[(dbase + d) * DOUT + c] = a[d];

    // qbk[d][h] = sum_c q[d][c] * bk[c] (head h covers cols 64h..64h+63)
    float bkc = bk[c];
    float p[4];
    #pragma unroll
    for (int d = 0; d < 4; d++) p[d] = a[d] * bkc;
    #pragma unroll
    for (int off = 16; off > 0; off >>= 1)
        #pragma unroll
        for (int d = 0; d < 4; d++)
            p[d] += __shfl_xor_sync(0xffffffffu, p[d], off);
    int warp = c >> 5;
    if ((c & 31) == 0)
        #pragma unroll
        for (int d = 0; d < 4; d++) part[d][warp] = p[d];
    __syncthreads();
    if (c < 8) {
        int d = c >> 1, hh = c & 1;
        g_qbk[(dbase + d) * 2 + hh] = part[d][hh * 2] + part[d][hh * 2 + 1];
    }
}

// ---------------- kernel 1b: Pq[d,k,h] = sum_c qn[d,64h+c] * wk[k,64h+c] ----
__global__ __launch_bounds__(256) void pq_kernel(const float* __restrict__ wk)
{
    __shared__ float qs[64][129];
    __shared__ float ws[64][129];
    int dbase = blockIdx.x * 64;
    int kbase = blockIdx.y * 64;
    int tid = threadIdx.x;
    for (int i = tid; i < 64 * 128; i += 256) {
        int r = i >> 7, c = i & 127;
        int d = dbase + r;
        qs[r][c] = (d < NUM_DST) ? g_qnodes[d * DOUT + c] : 0.f;
        int k = kbase + r;
        ws[r][c] = (k < KDIM) ? wk[k * DOUT + c] : 0.f;
    }
    __syncthreads();
    int tx = tid & 15, ty = tid >> 4;
    float acc[2][4][4];
    #pragma unroll
    for (int hh = 0; hh < 2; hh++)
        #pragma unroll
        for (int i = 0; i < 4; i++)
            #pragma unroll
            for (int j = 0; j < 4; j++) acc[hh][i][j] = 0.f;

    #pragma unroll 1
    for (int hh = 0; hh < 2; hh++) {
        for (int c = 0; c < 64; c++) {
            float q[4], w[4];
            #pragma unroll
            for (int i = 0; i < 4; i++) q[i] = qs[ty * 4 + i][hh * 64 + c];
            #pragma unroll
            for (int j = 0; j < 4; j++) w[j] = ws[tx * 4 + j][hh * 64 + c];
            #pragma unroll
            for (int i = 0; i < 4; i++)
                #pragma unroll
                for (int j = 0; j < 4; j++)
                    acc[hh][i][j] = fmaf(q[i], w[j], acc[hh][i][j]);
        }
    }
    #pragma unroll
    for (int i = 0; i < 4; i++) {
        int d = dbase + ty * 4 + i;
        if (d >= NUM_DST) continue;
        #pragma unroll
        for (int j = 0; j < 4; j++) {
            int k = kbase + tx * 4 + j;
            if (k >= KDIM) continue;
            g_Pq[((size_t)d * KDIM + k) * 2 + 0] = acc[0][i][j];
            g_Pq[((size_t)d * KDIM + k) * 2 + 1] = acc[1][i][j];
        }
    }
}

// ---------------- kernel 2a: scores + exp + z (one warp per edge) -----------
__global__ __launch_bounds__(256) void score_kernel(
    const float* __restrict__ h,   const float* __restrict__ ef,
    const float* __restrict__ dt,  const int*   __restrict__ dst_idx,
    const float* __restrict__ time_w, const float* __restrict__ time_b)
{
    int e = (blockIdx.x * 256 + threadIdx.x) >> 5;
    if (e >= NUM_EDGES) return;
    int lane = threadIdx.x & 31;
    float td = dt[e];
    int d = dst_idx[e];
    const float* __restrict__ hrow  = h + (size_t)(NUM_DST + e) * DN;
    const float* __restrict__ efrow = ef + (size_t)e * DE;

    // prefetch all kv values into registers (high MLP)
    float v[NKC];
    #pragma unroll
    for (int it = 0; it < NKC; it++) {
        int k = it * 32 + lane;
        float x = 0.f;
        if (k < DN)            x = hrow[k];
        else if (k < DN + DE)  x = efrow[k - DN];
        else if (k < KDIM) { int t = k - DN - DE; x = __cosf(td * time_w[t] + time_b[t]); }
        v[it] = x;
    }
    const float2* __restrict__ pq = (const float2*)(g_Pq + (size_t)d * KDIM * 2);
    float2 p[NKC];
    #pragma unroll
    for (int it = 0; it < NKC; it++) {
        int k = it * 32 + lane;
        p[it] = (k < KDIM) ? pq[k] : make_float2(0.f, 0.f);
    }
    float a0 = 0.f, a1 = 0.f;
    #pragma unroll
    for (int it = 0; it < NKC; it++) {
        a0 = fmaf(v[it], p[it].x, a0);
        a1 = fmaf(v[it], p[it].y, a1);
    }
    #pragma unroll
    for (int off = 16; off > 0; off >>= 1) {
        a0 += __shfl_xor_sync(0xffffffffu, a0, off);
        a1 += __shfl_xor_sync(0xffffffffu, a1, off);
    }
    if (lane == 0) {
        float s0 = a0 + g_absum[0] + g_qbk[d * 2 + 0];
        float s1 = a1 + g_absum[1] + g_qbk[d * 2 + 1];
        s0 = s0 > 0.f ? s0 : 0.2f * s0;
        s1 = s1 > 0.f ? s1 : 0.2f * s1;
        // softmax without max-subtraction: e^s / sum e^s (identical result)
        float e0 = __expf(fminf(s0, 80.f));
        float e1 = __expf(fminf(s1, 80.f));
        g_scores[e * 2 + 0] = e0;
        g_scores[e * 2 + 1] = e1;
        atomicAdd(&g_z[d * 2 + 0], e0);
        atomicAdd(&g_z[d * 2 + 1], e1);
    }
}

// ---------------- kernel 2b: persistent tf32-MMA V GEMM + aggregation -------
// B (wv, tf32) resident in smem [KPAD][128] XOR-swizzled. A double-buffered
// [128 edges][32 k] XOR-swizzled. 512 threads: wm=wid&3 (32-edge slice),
// wn=wid>>2 (32-col slice). Pipeline: LDG(kc+1) -> sync -> MMA(kc) -> STS(kc+1).
__global__ __launch_bounds__(512, 1) void vagg_kernel(
    const float* __restrict__ h,   const float* __restrict__ ef,
    const float* __restrict__ dt,  const int*   __restrict__ dst_idx,
    const float* __restrict__ time_w, const float* __restrict__ time_b,
    const float* __restrict__ wv)
{
    extern __shared__ float smem[];
    float* sB = smem;                         // KPAD*128 floats
    float* sA = smem + KPAD * DOUT;           // 2 * 128*32 floats
    const int tid  = threadIdx.x;
    const int lane = tid & 31;
    const int wid  = tid >> 5;
    const int wm   = wid & 3;
    const int wn   = wid >> 2;
    const int head = wn >> 1;

    // ---- load full wv into smem as tf32 (once per block) ----
    #pragma unroll 4
    for (int i = tid; i < KPAD * DOUT; i += 512) {
        int r = i >> 7, c = i & 127;
        float v = (r < KDIM) ? wv[r * DOUT + c] : 0.f;
        sB[r * DOUT + (c ^ ((r & 3) * 8))] = __uint_as_float(to_tf32(v));
    }

    for (int tile = blockIdx.x; tile < NTILES; tile += gridDim.x) {
        const int e_base = tile * ET2;

        float acc[2][4][4];
        #pragma unroll
        for (int mf = 0; mf < 2; mf++)
            #pragma unroll
            for (int nf = 0; nf < 4; nf++)
                #pragma unroll
                for (int r = 0; r < 4; r++) acc[mf][nf][r] = 0.f;

        float stage[8];
        // ---- prologue: chunk 0 into buf 0 ----
        #pragma unroll
        for (int rep = 0; rep < 8; rep++) {
            int i = tid + rep * 512;
            int el = i >> 5, k = i & 31;
            int e = e_base + el;
            float v = 0.f;
            if (e < NUM_EDGES) {
                if (k < DN) v = h[(size_t)(NUM_DST + e) * DN + k];
                else        v = ef[(size_t)e * DE + (k - DN)];
            }
            stage[rep] = v;
        }
        #pragma unroll
        for (int rep = 0; rep < 8; rep++) {
            int i = tid + rep * 512;
            int el = i >> 5, kl = i & 31;
            sA[el * 32 + (kl ^ ((el & 7) * 4))] = __uint_as_float(to_tf32(stage[rep]));
        }

        #pragma unroll 1
        for (int kc = 0; kc < NKC; kc++) {
            // issue gmem loads for chunk kc+1 (h/ef parts only)
            if (kc < NKC - 1) {
                #pragma unroll
                for (int rep = 0; rep < 8; rep++) {
                    int i = tid + rep * 512;
                    int el = i >> 5, kl = i & 31;
                    int k = (kc + 1) * 32 + kl;
                    int e = e_base + el;
                    float v = 0.f;
                    if (e < NUM_EDGES && k < DN + DE) {
                        if (k < DN) v = h[(size_t)(NUM_DST + e) * DN + k];
                        else        v = ef[(size_t)e * DE + (k - DN)];
                    }
                    stage[rep] = v;
                }
            }
            __syncthreads();   // chunk kc fully in smem; prev buffer free

            // ---- MMA on buffer kc&1 ----
            const float* A = sA + (kc & 1) * (ET2 * 32);
            #pragma unroll
            for (int ks = 0; ks < 4; ks++) {
                int arow = lane >> 2;
                int c0 = (lane & 3) + ks * 8;
                uint32_t a[2][4];
                #pragma unroll
                for (int mf = 0; mf < 2; mf++) {
                    int rb = wm * 32 + mf * 16 + arow;
                    int sw = (rb & 7) * 4;
                    a[mf][0] = __float_as_uint(A[rb * 32 + (c0 ^ sw)]);
                    a[mf][1] = __float_as_uint(A[(rb + 8) * 32 + (c0 ^ sw)]);
                    a[mf][2] = __float_as_uint(A[rb * 32 + ((c0 + 4) ^ sw)]);
                    a[mf][3] = __float_as_uint(A[(rb + 8) * 32 + ((c0 + 4) ^ sw)]);
                }
                uint32_t b[4][2];
                int brow = kc * 32 + (lane & 3) + ks * 8;
                int swb = (brow & 3) * 8;
                #pragma unroll
                for (int nf = 0; nf < 4; nf++) {
                    int bn = wn * 32 + nf * 8 + (lane >> 2);
                    b[nf][0] = __float_as_uint(sB[brow * DOUT + (bn ^ swb)]);
                    b[nf][1] = __float_as_uint(sB[(brow + 4) * DOUT + (bn ^ swb)]);
                }
                #pragma unroll
                for (int mf = 0; mf < 2; mf++)
                    #pragma unroll
                    for (int nf = 0; nf < 4; nf++) {
                        asm volatile(
                            "mma.sync.aligned.m16n8k8.row.col.f32.tf32.tf32.f32 "
                            "{%0,%1,%2,%3}, {%4,%5,%6,%7}, {%8,%9}, {%0,%1,%2,%3};"
                            : "+f"(acc[mf][nf][0]), "+f"(acc[mf][nf][1]),
                              "+f"(acc[mf][nf][2]), "+f"(acc[mf][nf][3])
                            : "r"(a[mf][0]), "r"(a[mf][1]), "r"(a[mf][2]), "r"(a[mf][3]),
                              "r"(b[nf][0]), "r"(b[nf][1]));
                    }
            }

            // ---- cvt + STS chunk kc+1 into other buffer (cos computed here) ----
            if (kc < NKC - 1) {
                float* An = sA + ((kc + 1) & 1) * (ET2 * 32);
                #pragma unroll
                for (int rep = 0; rep < 8; rep++) {
                    int i = tid + rep * 512;
                    int el = i >> 5, kl = i & 31;
                    int k = (kc + 1) * 32 + kl;
                    int e = e_base + el;
                    float v = stage[rep];
                    if (k >= DN + DE) {
                        v = 0.f;
                        if (e < NUM_EDGES && k < KDIM) {
                            int t = k - DN - DE;
                            v = __cosf(dt[e] * time_w[t] + time_b[t]);
                        }
                    }
                    An[el * 32 + (kl ^ ((el & 7) * 4))] = __uint_as_float(to_tf32(v));
                }
            }
        }
        __syncthreads();   // last mma done before next tile's prologue STS

        // ---- epilogue: scale by att, accumulate into g_agg ----
        #pragma unroll
        for (int mf = 0; mf < 2; mf++) {
            #pragma unroll
            for (int rs = 0; rs < 2; rs++) {
                int e = e_base + wm * 32 + mf * 16 + rs * 8 + (lane >> 2);
                if (e >= NUM_EDGES) continue;
                int d = dst_idx[e];
                float att = g_scores[e * 2 + head] / g_z[d * 2 + head];
                #pragma unroll
                for (int nf = 0; nf < 4; nf++) {
                    int col = wn * 32 + nf * 8 + 2 * (lane & 3);
                    float vx = acc[mf][nf][rs * 2 + 0] * att;
                    float vy = acc[mf][nf][rs * 2 + 1] * att;
                    float* ptr = &g_agg[d * DOUT + col];
                    asm volatile("red.global.add.v2.f32 [%0], {%1,%2};"
                                 :: "l"(ptr), "f"(vx), "f"(vy) : "memory");
                }
            }
        }
    }
}

// ---------------- kernel 5: output GEMM + relu + layernorm (4 dst/block) ----
__global__ __launch_bounds__(128) void out_kernel(
    const float* __restrict__ h,    const float* __restrict__ wout,
    const float* __restrict__ bout, const float* __restrict__ bv,
    const float* __restrict__ ln_g, const float* __restrict__ ln_b,
    float* __restrict__ out)
{
    int dbase = blockIdx.x * 4;
    int c = threadIdx.x;
    __shared__ float sin[4][DOUT + DN];
    __shared__ float red1[4][4], red2[4][4];
    for (int i = c; i < 4 * (DOUT + DN); i += 128) {
        int dl = i / (DOUT + DN), k = i - dl * (DOUT + DN);
        int d = dbase + dl;
        float v;
        if (k < DOUT)
            v = g_agg[d * DOUT + k] + (g_z[d * 2 + (k >> 6)] > 0.f ? bv[k] : 0.f);
        else
            v = h[(size_t)d * DN + (k - DOUT)];
        sin[dl][k] = v;
    }
    __syncthreads();

    float b0 = bout[c];
    float a[4] = {b0, b0, b0, b0};
    #pragma unroll 4
    for (int k = 0; k < DOUT + DN; k++) {
        float w = wout[k * DOUT + c];
        #pragma unroll
        for (int d = 0; d < 4; d++) a[d] = fmaf(sin[d][k], w, a[d]);
    }
    float s1[4], s2[4];
    #pragma unroll
    for (int d = 0; d < 4; d++) {
        a[d] = fmaxf(a[d], 0.f);
        s1[d] = a[d];
        s2[d] = a[d] * a[d];
    }
    #pragma unroll
    for (int off = 16; off > 0; off >>= 1) {
        #pragma unroll
        for (int d = 0; d < 4; d++) {
            s1[d] += __shfl_xor_sync(0xffffffffu, s1[d], off);
            s2[d] += __shfl_xor_sync(0xffffffffu, s2[d], off);
        }
    }
    int warp = c >> 5;
    if ((c & 31) == 0) {
        #pragma unroll
        for (int d = 0; d < 4; d++) { red1[d][warp] = s1[d]; red2[d][warp] = s2[d]; }
    }
    __syncthreads();
    #pragma unroll
    for (int d = 0; d < 4; d++) {
        float t1 = red1[d][0] + red1[d][1] + red1[d][2] + red1[d][3];
        float t2 = red2[d][0] + red2[d][1] + red2[d][2] + red2[d][3];
        float mu  = t1 * (1.f / DOUT);
        float var = t2 * (1.f / DOUT) - mu * mu;
        out[(size_t)(dbase + d) * DOUT + c] =
            (a[d] - mu) * rsqrtf(var + 1e-5f) * ln_g[c] + ln_b[c];
    }
}

// ---------------- launch ----------------------------------------------------
extern "C" void kernel_launch(void* const* d_in, const int* in_sizes, int n_in,
                              void* d_out, int out_size)
{
    int off = (n_in >= 18 && in_sizes[4] == 1) ? 1 : 0;
    const float* h        = (const float*)d_in[0];
    const float* ef       = (const float*)d_in[1];
    const float* dt       = (const float*)d_in[2];
    const int*   dst_idx  = (const int*)  d_in[3];
    const float* time_w   = (const float*)d_in[4 + off];
    const float* time_b   = (const float*)d_in[5 + off];
    const float* wq       = (const float*)d_in[6 + off];
    const float* bq       = (const float*)d_in[7 + off];
    const float* wk       = (const float*)d_in[8 + off];
    const float* bk       = (const float*)d_in[9 + off];
    const float* wv       = (const float*)d_in[10 + off];
    const float* bv       = (const float*)d_in[11 + off];
    const float* att_bias = (const float*)d_in[12 + off];
    const float* wout     = (const float*)d_in[13 + off];
    const float* bout     = (const float*)d_in[14 + off];
    const float* ln_g     = (const float*)d_in[15 + off];
    const float* ln_b     = (const float*)d_in[16 + off];
    float* out = (float*)d_out;

    cudaFuncSetAttribute(vagg_kernel,
                         cudaFuncAttributeMaxDynamicSharedMemorySize, VAGG_SMEM);

    init_kernel<<<(NUM_DST * DOUT + 255) / 256, 256>>>(time_b, wq, bq, att_bias);
    qnode_kernel<<<NUM_DST / 4, 128>>>(h, wq, bk);
    pq_kernel<<<dim3((NUM_DST + 63) / 64, (KDIM + 63) / 64), 256>>>(wk);
    score_kernel<<<NUM_EDGES / 8, 256>>>(h, ef, dt, dst_idx, time_w, time_b);
    vagg_kernel<<<VAGG_GRID, 512, VAGG_SMEM>>>(h, ef, dt, dst_idx,
                                               time_w, time_b, wv);
    out_kernel<<<NUM_DST / 4, 128>>>(h, wout, bout, bv, ln_g, ln_b, out);
}